// round 7
// baseline (speedup 1.0000x reference)
#include <cuda_runtime.h>
#include <cuda_bf16.h>
#include <math.h>
#include <stdint.h>

// ---------------------------------------------------------------------------
// Problem constants
// ---------------------------------------------------------------------------
#define BATCH 16
#define SEQL  128
#define IN_DIM 1218
#define HID 200          // H
#define G4  800          // 4*H
#define LSTMD 400
#define SMAX 8001        // (L-1)(L-2)/2
#define ML (BATCH*SEQL)  // 2048
#define OUT_BASE (BATCH*SMAX*LSTMD)  // 51,206,400

// ---------------------------------------------------------------------------
// Scratch (static device globals -- no runtime allocation).
// Referenced ONLY inside device code (host-shadow-address pitfall).
// ---------------------------------------------------------------------------
__device__ float g_emb[ML * IN_DIM];        // (b*L+t, 1218)
__device__ float g_gx [2 * ML * G4];        // [dir][b][t][800]  (reused both layers)
__device__ float g_h0 [ML * LSTMD];         // layer0 output [b][t][400]
__device__ float g_h1 [ML * LSTMD];         // layer1 output
__device__ float g_hx [2 * 32 * 208];       // h exchange [parity][pair][<=208]
__device__ int   g_bar[32];                 // per-(dir,b) step counters
__device__ int   g_lens[BATCH];
__device__ int   g_ij  [BATCH * SMAX];

// ---------------------------------------------------------------------------
// lens[b] = #(word_idxs != PAD).  Block 0 also zeroes the step counters.
// ---------------------------------------------------------------------------
__global__ void lens_kernel(const int* __restrict__ wi)
{
    int b = blockIdx.x, t = threadIdx.x;
    if (b == 0 && t < 32) g_bar[t] = 0;
    int v = (wi[b * SEQL + t] != 0) ? 1 : 0;
    int cnt = __syncthreads_count(v);
    if (t == 0) g_lens[b] = cnt;
}

// ---------------------------------------------------------------------------
// Embedding concat
// ---------------------------------------------------------------------------
__global__ void embed_kernel(const float* __restrict__ ext_emb,
                             const float* __restrict__ word_emb,
                             const float* __restrict__ pos_emb,
                             const float* __restrict__ dep_emb,
                             const float* __restrict__ ent_emb,
                             const float* __restrict__ iob_emb,
                             const float* __restrict__ bert,
                             const int* __restrict__ word_idxs,
                             const int* __restrict__ pos_idxs,
                             const int* __restrict__ dep_idxs,
                             const int* __restrict__ ent_idxs,
                             const int* __restrict__ iob_idxs)
{
    long idx = (long)blockIdx.x * blockDim.x + threadIdx.x;
    if (idx >= (long)ML * IN_DIM) return;
    int d  = (int)(idx % IN_DIM);
    int bt = (int)(idx / IN_DIM);
    float v;
    if (d < 300) {
        int wi  = word_idxs[bt];
        int wid = (wi >= 20000) ? 1 : wi;
        v = ext_emb[(size_t)wi * 300 + d] + word_emb[(size_t)wid * 300 + d];
    } else if (d < 350) {
        v = pos_emb[pos_idxs[bt] * 50 + (d - 300)];
    } else if (d < 400) {
        v = dep_emb[dep_idxs[bt] * 50 + (d - 350)];
    } else if (d < 425) {
        v = ent_emb[ent_idxs[bt] * 25 + (d - 400)];
    } else if (d < 450) {
        v = iob_emb[iob_idxs[bt] * 25 + (d - 425)];
    } else {
        v = bert[(size_t)bt * 768 + (d - 450)];
    }
    g_emb[idx] = v;
}

// ---------------------------------------------------------------------------
// tf32 tensor-core GEMM (unchanged from round 5 -- proven at rel_err 5e-4)
// ---------------------------------------------------------------------------
#define BM 128
#define BN 64
#define BK 16
#define ASTR 136
#define BSTR 72

__device__ __forceinline__ uint32_t f2tf32(float v)
{
    uint32_t r;
    asm("cvt.rna.tf32.f32 %0, %1;" : "=r"(r) : "f"(v));
    return r;
}

__global__ void __launch_bounds__(256)
gemm_tf32_kernel(const float* __restrict__ Wall,
                 const float* __restrict__ bih_all, const float* __restrict__ bhh_all,
                 int M, int N, int K, int src_sel)
{
    const float* A = src_sel ? g_h0 : g_emb;
    const int dir = blockIdx.z;
    const float* W  = Wall + (size_t)dir * N * K;
    const float* bi = bih_all + dir * N;
    const float* bh = bhh_all + dir * N;
    float* C = g_gx + (size_t)dir * M * N;

    __shared__ uint32_t As[2][BK][ASTR];
    __shared__ uint32_t Bs[2][BK][BSTR];

    const int tid  = threadIdx.x;
    const int m0   = blockIdx.y * BM;
    const int n0   = blockIdx.x * BN;
    const int warp = tid >> 5;
    const int lane = tid & 31;
    const int wm   = warp & 3;
    const int wn   = warp >> 2;
    const int gid  = lane >> 2;
    const int tig  = lane & 3;

    const int arow = tid >> 2;
    const int akq  = (tid & 3) * 4;

    float acc[2][4][4];
#pragma unroll
    for (int mi = 0; mi < 2; mi++)
#pragma unroll
        for (int ni = 0; ni < 4; ni++)
#pragma unroll
            for (int r = 0; r < 4; r++) acc[mi][ni][r] = 0.f;

    const int numk = (K + BK - 1) / BK;
    float aR[8], bR[4];

    {
        const int k0 = 0;
#pragma unroll
        for (int u = 0; u < 2; u++) {
            int m = m0 + arow + u * 64;
            const float* ap = A + (size_t)m * K + k0 + akq;
#pragma unroll
            for (int c = 0; c < 4; c++) {
                int kk = k0 + akq + c;
                aR[u * 4 + c] = (kk < K) ? ap[c] : 0.f;
            }
        }
        int n = n0 + arow;
        const float* wp = W + (size_t)n * K + k0 + akq;
#pragma unroll
        for (int c = 0; c < 4; c++) {
            int kk = k0 + akq + c;
            bR[c] = (n < N && kk < K) ? wp[c] : 0.f;
        }
    }

    for (int s = 0; s < numk; s++) {
        const int buf = s & 1;
#pragma unroll
        for (int u = 0; u < 2; u++)
#pragma unroll
            for (int c = 0; c < 4; c++)
                As[buf][akq + c][arow + u * 64] = f2tf32(aR[u * 4 + c]);
#pragma unroll
        for (int c = 0; c < 4; c++)
            Bs[buf][akq + c][arow] = f2tf32(bR[c]);
        __syncthreads();

        if (s + 1 < numk) {
            const int k0 = (s + 1) * BK;
#pragma unroll
            for (int u = 0; u < 2; u++) {
                int m = m0 + arow + u * 64;
                const float* ap = A + (size_t)m * K + k0 + akq;
#pragma unroll
                for (int c = 0; c < 4; c++) {
                    int kk = k0 + akq + c;
                    aR[u * 4 + c] = (kk < K) ? ap[c] : 0.f;
                }
            }
            int n = n0 + arow;
            const float* wp = W + (size_t)n * K + k0 + akq;
#pragma unroll
            for (int c = 0; c < 4; c++) {
                int kk = k0 + akq + c;
                bR[c] = (n < N && kk < K) ? wp[c] : 0.f;
            }
        }

#pragma unroll
        for (int kk = 0; kk < 2; kk++) {
            const int kb = kk * 8;
            uint32_t af[2][4];
#pragma unroll
            for (int mi = 0; mi < 2; mi++) {
                int m = wm * 32 + mi * 16 + gid;
                af[mi][0] = As[buf][kb + tig][m];
                af[mi][1] = As[buf][kb + tig][m + 8];
                af[mi][2] = As[buf][kb + tig + 4][m];
                af[mi][3] = As[buf][kb + tig + 4][m + 8];
            }
#pragma unroll
            for (int ni = 0; ni < 4; ni++) {
                int n = wn * 32 + ni * 8 + gid;
                uint32_t b0 = Bs[buf][kb + tig][n];
                uint32_t b1 = Bs[buf][kb + tig + 4][n];
#pragma unroll
                for (int mi = 0; mi < 2; mi++) {
                    asm volatile(
                        "mma.sync.aligned.m16n8k8.row.col.f32.tf32.tf32.f32 "
                        "{%0,%1,%2,%3},{%4,%5,%6,%7},{%8,%9},{%0,%1,%2,%3};"
                        : "+f"(acc[mi][ni][0]), "+f"(acc[mi][ni][1]),
                          "+f"(acc[mi][ni][2]), "+f"(acc[mi][ni][3])
                        : "r"(af[mi][0]), "r"(af[mi][1]),
                          "r"(af[mi][2]), "r"(af[mi][3]),
                          "r"(b0), "r"(b1));
                }
            }
        }
        __syncthreads();
    }

#pragma unroll
    for (int mi = 0; mi < 2; mi++) {
#pragma unroll
        for (int ni = 0; ni < 4; ni++) {
            int m = m0 + wm * 32 + mi * 16 + gid;
            int n = n0 + wn * 32 + ni * 8 + tig * 2;
            if (n < N) {
                float bs0 = bi[n] + bh[n];
                float bs1 = bi[n + 1] + bh[n + 1];
                float2 v0 = make_float2(acc[mi][ni][0] + bs0, acc[mi][ni][1] + bs1);
                float2 v1 = make_float2(acc[mi][ni][2] + bs0, acc[mi][ni][3] + bs1);
                *(float2*)&C[(size_t)m * N + n] = v0;
                *(float2*)&C[(size_t)(m + 8) * N + n] = v1;
            }
        }
    }
}

// ---------------------------------------------------------------------------
// Recurrence, 2-stream interleaved. 64 CTAs = 16 groups of 4 (NO clusters).
// Group g handles TWO streams sharing the same W_hh slice: (dir, b) and
// (dir, b+8), dir = g>>3, b = g&7. Rank r owns hidden units [r*50, r*50+50)
// (gate rows {q*200 + r*50 + jj}); W slice register-resident (50 float4/thr).
//
// Per step, per stream: dots -> gates -> stcg h slice -> bar ->
// tid0 red.release(+1 on per-stream counter). Stream B's compute overlaps
// stream A's L2 flag round-trip. Then all threads ld.acquire-spin on each
// counter and reload h into smem. Counters are monotonic (zeroed once in
// lens_kernel; layer1 uses base 512), so no reset between layers.
// ---------------------------------------------------------------------------
__device__ __forceinline__ void red_release(int* p)
{
    asm volatile("red.release.gpu.global.add.u32 [%0], 1;" :: "l"(p) : "memory");
}
__device__ __forceinline__ int ld_acquire(const int* p)
{
    int v;
    asm volatile("ld.acquire.gpu.global.u32 %0, [%1];" : "=r"(v) : "l"(p) : "memory");
    return v;
}

__global__ void __launch_bounds__(224, 1)
recur_kernel(const float* __restrict__ Whh,   // [2][800][200]
             int layer_sel)
{
    const int r    = (int)(blockIdx.x & 3);   // rank 0..3
    const int grp  = (int)(blockIdx.x >> 2);  // 0..15
    const int dir  = grp >> 3;
    const int b0   = grp & 7;
    const int b1   = b0 + 8;
    const int pair0 = dir * 16 + b0;
    const int pair1 = dir * 16 + b1;
    const int tid  = threadIdx.x;
    const int len0 = g_lens[b0];
    const int len1 = g_lens[b1];
    const int tbase = layer_sel ? 512 : 0;
    float* outh = layer_sel ? g_h1 : g_h0;

    __shared__ __align__(16) float hs0[200];
    __shared__ __align__(16) float hs1[200];
    __shared__ float dots0[200];
    __shared__ float dots1[200];

    // W_hh slice -> registers
    float4 W4[50];
    int grow = 0;
    if (tid < 200) {
        int q = tid / 50, jj = tid % 50;
        grow = q * 200 + r * 50 + jj;
        const float4* wp = (const float4*)(Whh + ((size_t)dir * G4 + grow) * HID);
#pragma unroll
        for (int kk = 0; kk < 50; kk++) W4[kk] = wp[kk];
    }
    if (tid < 200) { hs0[tid] = 0.f; hs1[tid] = 0.f; }
    float c0 = 0.f, c1 = 0.f;

    const long gstep = dir ? -(long)G4 : (long)G4;
    const int  tp0   = dir ? (SEQL - 1) : 0;
    const float* gp0 = g_gx + ((size_t)dir * BATCH + b0) * SEQL * G4 + (size_t)tp0 * G4 + grow;
    const float* gp1 = g_gx + ((size_t)dir * BATCH + b1) * SEQL * G4 + (size_t)tp0 * G4 + grow;
    float gcur0 = 0.f, gcur1 = 0.f;
    if (tid < 200) { gcur0 = *gp0; gcur1 = *gp1; }
    __syncthreads();

    for (int t = 0; t < SEQL; t++) {
        const int tp  = dir ? (SEQL - 1 - t) : t;
        const int par = t & 1;
        const float mt0 = (tp < len0) ? 1.f : 0.f;
        const float mt1 = (tp < len1) ? 1.f : 0.f;

        // ---- stream 0 dots ----
        if (tid < 200) {
            const float4* h4 = (const float4*)hs0;
            float a0 = 0.f, a1 = 0.f, a2 = 0.f, a3 = 0.f;
#pragma unroll
            for (int kk = 0; kk < 50; kk++) {
                float4 hv = h4[kk];
                a0 += W4[kk].x * hv.x;
                a1 += W4[kk].y * hv.y;
                a2 += W4[kk].z * hv.z;
                a3 += W4[kk].w * hv.w;
            }
            dots0[tid] = (a0 + a1) + (a2 + a3) + gcur0;
            gp0 += gstep;
            if (t + 1 < SEQL) gcur0 = __ldcg(gp0);
        }
        __syncthreads();

        // ---- stream 0 gates + publish ----
        if (tid < 50) {
            float gi = dots0[tid];
            float gf = dots0[50 + tid];
            float gg = dots0[100 + tid];
            float go = dots0[150 + tid];
            float si = 1.f / (1.f + __expf(-gi));
            float sf = 1.f / (1.f + __expf(-gf));
            float so = 1.f / (1.f + __expf(-go));
            float cn = sf * c0 + si * tanhf(gg);
            float hn = so * tanhf(cn);
            int gu = r * 50 + tid;
            float hp = hs0[gu];
            float hnew = mt0 * hn + (1.f - mt0) * hp;
            c0 = mt0 * cn + (1.f - mt0) * c0;
            outh[((size_t)b0 * SEQL + tp) * LSTMD + dir * HID + gu] = mt0 * hn;
            __stcg(g_hx + ((size_t)par * 32 + pair0) * 208 + gu, hnew);
        }
        __syncthreads();
        if (tid == 0) red_release(&g_bar[pair0]);

        // ---- stream 1 dots (overlaps stream 0's flag round-trip) ----
        if (tid < 200) {
            const float4* h4 = (const float4*)hs1;
            float a0 = 0.f, a1 = 0.f, a2 = 0.f, a3 = 0.f;
#pragma unroll
            for (int kk = 0; kk < 50; kk++) {
                float4 hv = h4[kk];
                a0 += W4[kk].x * hv.x;
                a1 += W4[kk].y * hv.y;
                a2 += W4[kk].z * hv.z;
                a3 += W4[kk].w * hv.w;
            }
            dots1[tid] = (a0 + a1) + (a2 + a3) + gcur1;
            gp1 += gstep;
            if (t + 1 < SEQL) gcur1 = __ldcg(gp1);
        }
        __syncthreads();

        // ---- stream 1 gates + publish ----
        if (tid < 50) {
            float gi = dots1[tid];
            float gf = dots1[50 + tid];
            float gg = dots1[100 + tid];
            float go = dots1[150 + tid];
            float si = 1.f / (1.f + __expf(-gi));
            float sf = 1.f / (1.f + __expf(-gf));
            float so = 1.f / (1.f + __expf(-go));
            float cn = sf * c1 + si * tanhf(gg);
            float hn = so * tanhf(cn);
            int gu = r * 50 + tid;
            float hp = hs1[gu];
            float hnew = mt1 * hn + (1.f - mt1) * hp;
            c1 = mt1 * cn + (1.f - mt1) * c1;
            outh[((size_t)b1 * SEQL + tp) * LSTMD + dir * HID + gu] = mt1 * hn;
            __stcg(g_hx + ((size_t)par * 32 + pair1) * 208 + gu, hnew);
        }
        __syncthreads();
        if (tid == 0) red_release(&g_bar[pair1]);

        // ---- wait + reload both streams ----
        {
            const int target = tbase + 4 * (t + 1);
            while (ld_acquire(&g_bar[pair0]) < target) { }
            if (tid < 200)
                hs0[tid] = __ldcg(g_hx + ((size_t)par * 32 + pair0) * 208 + tid);
            while (ld_acquire(&g_bar[pair1]) < target) { }
            if (tid < 200)
                hs1[tid] = __ldcg(g_hx + ((size_t)par * 32 + pair1) * 208 + tid);
        }
        __syncthreads();
    }
}

// ---------------------------------------------------------------------------
// s -> (i,j) table. Valid pairs for batch b: 0 <= i < j < n,  n = lens[b]-1.
// Also writes the lens-2 output tail.
// ---------------------------------------------------------------------------
__global__ void ij_kernel(float* __restrict__ out, int extra)
{
    int idx = blockIdx.x * blockDim.x + threadIdx.x;
    if (idx < extra && idx < BATCH)
        out[(size_t)OUT_BASE + idx] = (float)(g_lens[idx] - 2);
    if (idx >= BATCH * SMAX) return;
    int s = idx % SMAX;
    int b = idx / SMAX;
    int n = g_lens[b] - 1;
    int cnt = n * (n - 1) / 2;
    int val = 0;
    if (s < cnt) {
        float fn = (float)(2 * n - 1);
        int i = (int)floorf((fn - sqrtf(fn * fn - 8.0f * (float)s)) * 0.5f);
        if (i < 0) i = 0;
        if (i > n - 2) i = n - 2;
        while ((i + 1) * (2 * n - 2 - i) / 2 <= s) i++;
        while (i > 0 && i * (2 * n - 1 - i) / 2 > s) i--;
        int j = i + 1 + (s - i * (2 * n - 1 - i) / 2);
        val = (i << 8) | j;
    }
    g_ij[idx] = val;
}

// ---------------------------------------------------------------------------
// Span emit (float4 granularity)
// ---------------------------------------------------------------------------
__global__ void span_kernel(float* __restrict__ out)
{
    long idx = (long)blockIdx.x * blockDim.x + threadIdx.x; // over 16*8001*100
    if (idx >= (long)BATCH * SMAX * 100) return;
    int d4 = (int)(idx % 100);
    int bs = (int)(idx / 100);
    int s = bs % SMAX;
    int b = bs / SMAX;
    int n = g_lens[b] - 1;
    int cnt = n * (n - 1) / 2;
    float4 v = make_float4(0.f, 0.f, 0.f, 0.f);
    if (s < cnt) {
        int p = g_ij[bs];
        int i = p >> 8;
        int j = p & 255;
        const float4* hb = (const float4*)(g_h1 + (size_t)b * SEQL * LSTMD);
        float4 x, y;
        if (d4 < 50) {
            x = hb[j * 100 + d4];
            y = hb[i * 100 + d4];
        } else {
            x = hb[(i + 1) * 100 + d4];
            y = hb[(j + 1) * 100 + d4];
        }
        v.x = x.x - y.x; v.y = x.y - y.y; v.z = x.z - y.z; v.w = x.w - y.w;
    }
    ((float4*)out)[idx] = v;
}

// ---------------------------------------------------------------------------
// Launch
// ---------------------------------------------------------------------------
extern "C" void kernel_launch(void* const* d_in, const int* in_sizes, int n_in,
                              void* d_out, int out_size)
{
    const float* ext_emb  = (const float*)d_in[0];
    const float* word_emb = (const float*)d_in[1];
    const float* pos_emb  = (const float*)d_in[2];
    const float* dep_emb  = (const float*)d_in[3];
    const float* ent_emb  = (const float*)d_in[4];
    const float* iob_emb  = (const float*)d_in[5];
    const float* w_ih_l0  = (const float*)d_in[6];
    const float* w_hh_l0  = (const float*)d_in[7];
    const float* b_ih_l0  = (const float*)d_in[8];
    const float* b_hh_l0  = (const float*)d_in[9];
    const float* w_ih_l1  = (const float*)d_in[10];
    const float* w_hh_l1  = (const float*)d_in[11];
    const float* b_ih_l1  = (const float*)d_in[12];
    const float* b_hh_l1  = (const float*)d_in[13];
    const float* bert     = (const float*)d_in[14];
    const int* word_idxs  = (const int*)d_in[15];
    const int* pos_idxs   = (const int*)d_in[16];
    const int* dep_idxs   = (const int*)d_in[17];
    const int* ent_idxs   = (const int*)d_in[18];
    const int* iob_idxs   = (const int*)d_in[19];
    float* out = (float*)d_out;

    // 1. lengths + counter reset
    lens_kernel<<<BATCH, SEQL>>>(word_idxs);

    // 2. embedding concat
    {
        long tot = (long)ML * IN_DIM;
        int blocks = (int)((tot + 255) / 256);
        embed_kernel<<<blocks, 256>>>(ext_emb, word_emb, pos_emb, dep_emb,
                                      ent_emb, iob_emb, bert,
                                      word_idxs, pos_idxs, dep_idxs,
                                      ent_idxs, iob_idxs);
    }

    // 3. layer0 input projection  (M=2048, N=800, K=1218), A = g_emb
    {
        dim3 grid((G4 + BN - 1) / BN, ML / BM, 2);
        gemm_tf32_kernel<<<grid, 256>>>(w_ih_l0, b_ih_l0, b_hh_l0,
                                        ML, G4, IN_DIM, 0);
    }

    // 4. layer0 recurrence (64 CTAs, 16 groups x 4, 2 streams each)
    recur_kernel<<<64, 224>>>(w_hh_l0, 0);

    // 5. layer1 input projection (M=2048, N=800, K=400), A = g_h0
    {
        dim3 grid((G4 + BN - 1) / BN, ML / BM, 2);
        gemm_tf32_kernel<<<grid, 256>>>(w_ih_l1, b_ih_l1, b_hh_l1,
                                        ML, G4, LSTMD, 1);
    }

    // 6. layer1 recurrence
    recur_kernel<<<64, 224>>>(w_hh_l1, 1);

    // 7. s -> (i,j) table (+ lens-2 tail if present)
    {
        int extra = out_size - OUT_BASE;
        if (extra < 0) extra = 0;
        int tot = BATCH * SMAX;
        ij_kernel<<<(tot + 255) / 256, 256>>>(out, extra);
    }

    // 8. span emit
    {
        long tot = (long)BATCH * SMAX * 100;
        int blocks = (int)((tot + 255) / 256);
        span_kernel<<<blocks, 256>>>(out);
    }
}

// round 8
// speedup vs baseline: 1.2374x; 1.2374x over previous
#include <cuda_runtime.h>
#include <cuda_bf16.h>
#include <math.h>
#include <stdint.h>

// ---------------------------------------------------------------------------
// Problem constants
// ---------------------------------------------------------------------------
#define BATCH 16
#define SEQL  128
#define IN_DIM 1218
#define HID 200          // H
#define G4  800          // 4*H
#define LSTMD 400
#define SMAX 8001        // (L-1)(L-2)/2
#define ML (BATCH*SEQL)  // 2048
#define OUT_BASE (BATCH*SMAX*LSTMD)  // 51,206,400

// ---------------------------------------------------------------------------
// Scratch (static device globals -- no runtime allocation).
// Referenced ONLY inside device code (host-shadow-address pitfall).
// ---------------------------------------------------------------------------
__device__ float g_emb[ML * IN_DIM];        // (b*L+t, 1218)
__device__ float g_gx [2 * ML * G4];        // [dir][b][t][800]  (reused both layers)
__device__ float g_h0 [ML * LSTMD];         // layer0 output [b][t][400]
__device__ float g_h1 [ML * LSTMD];         // layer1 output
__device__ float g_hx [2 * 32 * 208];       // h exchange [parity][pair][<=208]
__device__ int   g_bar[32 * 64];            // step counters, ONE PER 256B LINE
__device__ int   g_lens[BATCH];
__device__ int   g_ij  [BATCH * SMAX];

// ---------------------------------------------------------------------------
// lens[b] = #(word_idxs != PAD).  Block 0 also zeroes the (padded) counters.
// ---------------------------------------------------------------------------
__global__ void lens_kernel(const int* __restrict__ wi)
{
    int b = blockIdx.x, t = threadIdx.x;
    if (b == 0 && t < 32) g_bar[t * 64] = 0;
    int v = (wi[b * SEQL + t] != 0) ? 1 : 0;
    int cnt = __syncthreads_count(v);
    if (t == 0) g_lens[b] = cnt;
}

// ---------------------------------------------------------------------------
// Embedding concat
// ---------------------------------------------------------------------------
__global__ void embed_kernel(const float* __restrict__ ext_emb,
                             const float* __restrict__ word_emb,
                             const float* __restrict__ pos_emb,
                             const float* __restrict__ dep_emb,
                             const float* __restrict__ ent_emb,
                             const float* __restrict__ iob_emb,
                             const float* __restrict__ bert,
                             const int* __restrict__ word_idxs,
                             const int* __restrict__ pos_idxs,
                             const int* __restrict__ dep_idxs,
                             const int* __restrict__ ent_idxs,
                             const int* __restrict__ iob_idxs)
{
    long idx = (long)blockIdx.x * blockDim.x + threadIdx.x;
    if (idx >= (long)ML * IN_DIM) return;
    int d  = (int)(idx % IN_DIM);
    int bt = (int)(idx / IN_DIM);
    float v;
    if (d < 300) {
        int wi  = word_idxs[bt];
        int wid = (wi >= 20000) ? 1 : wi;
        v = ext_emb[(size_t)wi * 300 + d] + word_emb[(size_t)wid * 300 + d];
    } else if (d < 350) {
        v = pos_emb[pos_idxs[bt] * 50 + (d - 300)];
    } else if (d < 400) {
        v = dep_emb[dep_idxs[bt] * 50 + (d - 350)];
    } else if (d < 425) {
        v = ent_emb[ent_idxs[bt] * 25 + (d - 400)];
    } else if (d < 450) {
        v = iob_emb[iob_idxs[bt] * 25 + (d - 425)];
    } else {
        v = bert[(size_t)bt * 768 + (d - 450)];
    }
    g_emb[idx] = v;
}

// ---------------------------------------------------------------------------
// tf32 tensor-core GEMM (unchanged -- proven at rel_err 5e-4)
// ---------------------------------------------------------------------------
#define BM 128
#define BN 64
#define BK 16
#define ASTR 136
#define BSTR 72

__device__ __forceinline__ uint32_t f2tf32(float v)
{
    uint32_t r;
    asm("cvt.rna.tf32.f32 %0, %1;" : "=r"(r) : "f"(v));
    return r;
}

__global__ void __launch_bounds__(256)
gemm_tf32_kernel(const float* __restrict__ Wall,
                 const float* __restrict__ bih_all, const float* __restrict__ bhh_all,
                 int M, int N, int K, int src_sel)
{
    const float* A = src_sel ? g_h0 : g_emb;
    const int dir = blockIdx.z;
    const float* W  = Wall + (size_t)dir * N * K;
    const float* bi = bih_all + dir * N;
    const float* bh = bhh_all + dir * N;
    float* C = g_gx + (size_t)dir * M * N;

    __shared__ uint32_t As[2][BK][ASTR];
    __shared__ uint32_t Bs[2][BK][BSTR];

    const int tid  = threadIdx.x;
    const int m0   = blockIdx.y * BM;
    const int n0   = blockIdx.x * BN;
    const int warp = tid >> 5;
    const int lane = tid & 31;
    const int wm   = warp & 3;
    const int wn   = warp >> 2;
    const int gid  = lane >> 2;
    const int tig  = lane & 3;

    const int arow = tid >> 2;
    const int akq  = (tid & 3) * 4;

    float acc[2][4][4];
#pragma unroll
    for (int mi = 0; mi < 2; mi++)
#pragma unroll
        for (int ni = 0; ni < 4; ni++)
#pragma unroll
            for (int r = 0; r < 4; r++) acc[mi][ni][r] = 0.f;

    const int numk = (K + BK - 1) / BK;
    float aR[8], bR[4];

    {
        const int k0 = 0;
#pragma unroll
        for (int u = 0; u < 2; u++) {
            int m = m0 + arow + u * 64;
            const float* ap = A + (size_t)m * K + k0 + akq;
#pragma unroll
            for (int c = 0; c < 4; c++) {
                int kk = k0 + akq + c;
                aR[u * 4 + c] = (kk < K) ? ap[c] : 0.f;
            }
        }
        int n = n0 + arow;
        const float* wp = W + (size_t)n * K + k0 + akq;
#pragma unroll
        for (int c = 0; c < 4; c++) {
            int kk = k0 + akq + c;
            bR[c] = (n < N && kk < K) ? wp[c] : 0.f;
        }
    }

    for (int s = 0; s < numk; s++) {
        const int buf = s & 1;
#pragma unroll
        for (int u = 0; u < 2; u++)
#pragma unroll
            for (int c = 0; c < 4; c++)
                As[buf][akq + c][arow + u * 64] = f2tf32(aR[u * 4 + c]);
#pragma unroll
        for (int c = 0; c < 4; c++)
            Bs[buf][akq + c][arow] = f2tf32(bR[c]);
        __syncthreads();

        if (s + 1 < numk) {
            const int k0 = (s + 1) * BK;
#pragma unroll
            for (int u = 0; u < 2; u++) {
                int m = m0 + arow + u * 64;
                const float* ap = A + (size_t)m * K + k0 + akq;
#pragma unroll
                for (int c = 0; c < 4; c++) {
                    int kk = k0 + akq + c;
                    aR[u * 4 + c] = (kk < K) ? ap[c] : 0.f;
                }
            }
            int n = n0 + arow;
            const float* wp = W + (size_t)n * K + k0 + akq;
#pragma unroll
            for (int c = 0; c < 4; c++) {
                int kk = k0 + akq + c;
                bR[c] = (n < N && kk < K) ? wp[c] : 0.f;
            }
        }

#pragma unroll
        for (int kk = 0; kk < 2; kk++) {
            const int kb = kk * 8;
            uint32_t af[2][4];
#pragma unroll
            for (int mi = 0; mi < 2; mi++) {
                int m = wm * 32 + mi * 16 + gid;
                af[mi][0] = As[buf][kb + tig][m];
                af[mi][1] = As[buf][kb + tig][m + 8];
                af[mi][2] = As[buf][kb + tig + 4][m];
                af[mi][3] = As[buf][kb + tig + 4][m + 8];
            }
#pragma unroll
            for (int ni = 0; ni < 4; ni++) {
                int n = wn * 32 + ni * 8 + gid;
                uint32_t b0 = Bs[buf][kb + tig][n];
                uint32_t b1 = Bs[buf][kb + tig + 4][n];
#pragma unroll
                for (int mi = 0; mi < 2; mi++) {
                    asm volatile(
                        "mma.sync.aligned.m16n8k8.row.col.f32.tf32.tf32.f32 "
                        "{%0,%1,%2,%3},{%4,%5,%6,%7},{%8,%9},{%0,%1,%2,%3};"
                        : "+f"(acc[mi][ni][0]), "+f"(acc[mi][ni][1]),
                          "+f"(acc[mi][ni][2]), "+f"(acc[mi][ni][3])
                        : "r"(af[mi][0]), "r"(af[mi][1]),
                          "r"(af[mi][2]), "r"(af[mi][3]),
                          "r"(b0), "r"(b1));
                }
            }
        }
        __syncthreads();
    }

#pragma unroll
    for (int mi = 0; mi < 2; mi++) {
#pragma unroll
        for (int ni = 0; ni < 4; ni++) {
            int m = m0 + wm * 32 + mi * 16 + gid;
            int n = n0 + wn * 32 + ni * 8 + tig * 2;
            if (n < N) {
                float bs0 = bi[n] + bh[n];
                float bs1 = bi[n + 1] + bh[n + 1];
                float2 v0 = make_float2(acc[mi][ni][0] + bs0, acc[mi][ni][1] + bs1);
                float2 v1 = make_float2(acc[mi][ni][2] + bs0, acc[mi][ni][3] + bs1);
                *(float2*)&C[(size_t)m * N + n] = v0;
                *(float2*)&C[(size_t)(m + 8) * N + n] = v1;
            }
        }
    }
}

// ---------------------------------------------------------------------------
// Recurrence (round-5 structure + contention fixes).
// 128 CTAs = 32 groups of 4; group = (dir,b) pair; rank r owns hidden units
// [r*50, r*50+50) (gate rows {q*200 + r*50 + jj}); W_hh slice in registers.
//
// Per-step sync protocol (fence-fence pattern, tid0 only):
//   writers stcg h slice -> bar.sync -> tid0: fence.acq_rel.gpu,
//   red.relaxed +1 on this pair's PADDED counter (1 per 256B line) ->
//   tid0 relaxed-polls counter to 4(t+1) -> fence.acq_rel.gpu -> bar.sync ->
//   all threads ldcg h. Counters monotonic across layers (layer1 base 512).
// ---------------------------------------------------------------------------
__device__ __forceinline__ void fence_acqrel_gpu()
{
    asm volatile("fence.acq_rel.gpu;" ::: "memory");
}
__device__ __forceinline__ void red_relaxed_add(int* p)
{
    asm volatile("red.relaxed.gpu.global.add.u32 [%0], 1;" :: "l"(p) : "memory");
}
__device__ __forceinline__ int ld_relaxed(const int* p)
{
    int v;
    asm volatile("ld.relaxed.gpu.global.u32 %0, [%1];" : "=r"(v) : "l"(p) : "memory");
    return v;
}

__global__ void __launch_bounds__(224, 1)
recur_kernel(const float* __restrict__ Whh,   // [2][800][200]
             int layer_sel)
{
    const int r    = (int)(blockIdx.x & 3);   // rank in group 0..3
    const int pair = (int)(blockIdx.x >> 2);  // 0..31
    const int dir  = pair >> 4;
    const int b    = pair & 15;
    const int tid  = threadIdx.x;
    const int len  = g_lens[b];
    const int tbase = layer_sel ? 512 : 0;
    int* cnt = &g_bar[pair * 64];
    float* outh = layer_sel ? g_h1 : g_h0;

    __shared__ float4 hs4[50];
    float* hs = (float*)hs4;
    __shared__ float dots[200];

    // Load W_hh slice into registers
    float4 W4[50];
    int grow = 0;
    if (tid < 200) {
        int q = tid / 50, jj = tid % 50;
        grow = q * 200 + r * 50 + jj;
        const float4* wp = (const float4*)(Whh + ((size_t)dir * G4 + grow) * HID);
#pragma unroll
        for (int kk = 0; kk < 50; kk++) W4[kk] = wp[kk];
    }
    if (tid < 50) hs4[tid] = make_float4(0.f, 0.f, 0.f, 0.f);

    float c = 0.f;
    const long gstep = dir ? -(long)G4 : (long)G4;
    const int  tpf   = dir ? (SEQL - 1) : 0;
    const float* gp  = g_gx + ((size_t)dir * BATCH + b) * SEQL * G4
                            + (size_t)tpf * G4 + grow;
    float gcur = 0.f;
    if (tid < 200) gcur = __ldcg(gp);
    __syncthreads();

    for (int t = 0; t < SEQL; t++) {
        const int tp  = dir ? (SEQL - 1 - t) : t;
        const int par = t & 1;
        const float mt = (tp < len) ? 1.f : 0.f;

        // dots = W_slice . h + gx   (200 active threads)
        if (tid < 200) {
            float a0 = 0.f, a1 = 0.f, a2 = 0.f, a3 = 0.f;
#pragma unroll
            for (int kk = 0; kk < 50; kk++) {
                float4 hv = hs4[kk];
                a0 += W4[kk].x * hv.x;
                a1 += W4[kk].y * hv.y;
                a2 += W4[kk].z * hv.z;
                a3 += W4[kk].w * hv.w;
            }
            dots[tid] = (a0 + a1) + (a2 + a3) + gcur;
            gp += gstep;
            if (t + 1 < SEQL) gcur = __ldcg(gp);   // prefetch next step's gx
        }
        __syncthreads();

        // gates + publish own 50-unit slice
        if (tid < 50) {
            float gi = dots[tid];
            float gf = dots[50 + tid];
            float gg = dots[100 + tid];
            float go = dots[150 + tid];
            float si = 1.f / (1.f + __expf(-gi));
            float sf = 1.f / (1.f + __expf(-gf));
            float so = 1.f / (1.f + __expf(-go));
            float cn = sf * c + si * tanhf(gg);
            float hn = so * tanhf(cn);
            int gu = r * 50 + tid;
            float hp = hs[gu];
            float hnew = mt * hn + (1.f - mt) * hp;
            c = mt * cn + (1.f - mt) * c;
            outh[((size_t)b * SEQL + tp) * LSTMD + dir * HID + gu] = mt * hn;
            __stcg(g_hx + ((size_t)par * 32 + pair) * 208 + gu, hnew);
        }
        __syncthreads();

        // arrive + wait (tid0 only; fence-fence synchronization)
        if (tid == 0) {
            fence_acqrel_gpu();
            red_relaxed_add(cnt);
            const int target = tbase + 4 * (t + 1);
            while (ld_relaxed(cnt) < target) { }
            fence_acqrel_gpu();
        }
        __syncthreads();

        // reload full h
        if (tid < 200)
            hs[tid] = __ldcg(g_hx + ((size_t)par * 32 + pair) * 208 + tid);
        __syncthreads();
    }
}

// ---------------------------------------------------------------------------
// s -> (i,j) table + lens-2 tail
// ---------------------------------------------------------------------------
__global__ void ij_kernel(float* __restrict__ out, int extra)
{
    int idx = blockIdx.x * blockDim.x + threadIdx.x;
    if (idx < extra && idx < BATCH)
        out[(size_t)OUT_BASE + idx] = (float)(g_lens[idx] - 2);
    if (idx >= BATCH * SMAX) return;
    int s = idx % SMAX;
    int b = idx / SMAX;
    int n = g_lens[b] - 1;
    int cnt = n * (n - 1) / 2;
    int val = 0;
    if (s < cnt) {
        float fn = (float)(2 * n - 1);
        int i = (int)floorf((fn - sqrtf(fn * fn - 8.0f * (float)s)) * 0.5f);
        if (i < 0) i = 0;
        if (i > n - 2) i = n - 2;
        while ((i + 1) * (2 * n - 2 - i) / 2 <= s) i++;
        while (i > 0 && i * (2 * n - 1 - i) / 2 > s) i--;
        int j = i + 1 + (s - i * (2 * n - 1 - i) / 2);
        val = (i << 8) | j;
    }
    g_ij[idx] = val;
}

// ---------------------------------------------------------------------------
// Span emit (float4 granularity)
// ---------------------------------------------------------------------------
__global__ void span_kernel(float* __restrict__ out)
{
    long idx = (long)blockIdx.x * blockDim.x + threadIdx.x; // over 16*8001*100
    if (idx >= (long)BATCH * SMAX * 100) return;
    int d4 = (int)(idx % 100);
    int bs = (int)(idx / 100);
    int s = bs % SMAX;
    int b = bs / SMAX;
    int n = g_lens[b] - 1;
    int cnt = n * (n - 1) / 2;
    float4 v = make_float4(0.f, 0.f, 0.f, 0.f);
    if (s < cnt) {
        int p = g_ij[bs];
        int i = p >> 8;
        int j = p & 255;
        const float4* hb = (const float4*)(g_h1 + (size_t)b * SEQL * LSTMD);
        float4 x, y;
        if (d4 < 50) {
            x = hb[j * 100 + d4];
            y = hb[i * 100 + d4];
        } else {
            x = hb[(i + 1) * 100 + d4];
            y = hb[(j + 1) * 100 + d4];
        }
        v.x = x.x - y.x; v.y = x.y - y.y; v.z = x.z - y.z; v.w = x.w - y.w;
    }
    ((float4*)out)[idx] = v;
}

// ---------------------------------------------------------------------------
// Launch
// ---------------------------------------------------------------------------
extern "C" void kernel_launch(void* const* d_in, const int* in_sizes, int n_in,
                              void* d_out, int out_size)
{
    const float* ext_emb  = (const float*)d_in[0];
    const float* word_emb = (const float*)d_in[1];
    const float* pos_emb  = (const float*)d_in[2];
    const float* dep_emb  = (const float*)d_in[3];
    const float* ent_emb  = (const float*)d_in[4];
    const float* iob_emb  = (const float*)d_in[5];
    const float* w_ih_l0  = (const float*)d_in[6];
    const float* w_hh_l0  = (const float*)d_in[7];
    const float* b_ih_l0  = (const float*)d_in[8];
    const float* b_hh_l0  = (const float*)d_in[9];
    const float* w_ih_l1  = (const float*)d_in[10];
    const float* w_hh_l1  = (const float*)d_in[11];
    const float* b_ih_l1  = (const float*)d_in[12];
    const float* b_hh_l1  = (const float*)d_in[13];
    const float* bert     = (const float*)d_in[14];
    const int* word_idxs  = (const int*)d_in[15];
    const int* pos_idxs   = (const int*)d_in[16];
    const int* dep_idxs   = (const int*)d_in[17];
    const int* ent_idxs   = (const int*)d_in[18];
    const int* iob_idxs   = (const int*)d_in[19];
    float* out = (float*)d_out;

    // 1. lengths + padded counter reset
    lens_kernel<<<BATCH, SEQL>>>(word_idxs);

    // 2. embedding concat
    {
        long tot = (long)ML * IN_DIM;
        int blocks = (int)((tot + 255) / 256);
        embed_kernel<<<blocks, 256>>>(ext_emb, word_emb, pos_emb, dep_emb,
                                      ent_emb, iob_emb, bert,
                                      word_idxs, pos_idxs, dep_idxs,
                                      ent_idxs, iob_idxs);
    }

    // 3. layer0 input projection  (M=2048, N=800, K=1218), A = g_emb
    {
        dim3 grid((G4 + BN - 1) / BN, ML / BM, 2);
        gemm_tf32_kernel<<<grid, 256>>>(w_ih_l0, b_ih_l0, b_hh_l0,
                                        ML, G4, IN_DIM, 0);
    }

    // 4. layer0 recurrence (128 CTAs, 32 groups x 4)
    recur_kernel<<<128, 224>>>(w_hh_l0, 0);

    // 5. layer1 input projection (M=2048, N=800, K=400), A = g_h0
    {
        dim3 grid((G4 + BN - 1) / BN, ML / BM, 2);
        gemm_tf32_kernel<<<grid, 256>>>(w_ih_l1, b_ih_l1, b_hh_l1,
                                        ML, G4, LSTMD, 1);
    }

    // 6. layer1 recurrence
    recur_kernel<<<128, 224>>>(w_hh_l1, 1);

    // 7. s -> (i,j) table (+ lens-2 tail if present)
    {
        int extra = out_size - OUT_BASE;
        if (extra < 0) extra = 0;
        int tot = BATCH * SMAX;
        ij_kernel<<<(tot + 255) / 256, 256>>>(out, extra);
    }

    // 8. span emit
    {
        long tot = (long)BATCH * SMAX * 100;
        int blocks = (int)((tot + 255) / 256);
        span_kernel<<<blocks, 256>>>(out);
    }
}